// round 2
// baseline (speedup 1.0000x reference)
#include <cuda_runtime.h>
#include <math.h>
#include <stdint.h>

#define H 2048
#define NOPS 8
#define NNODES 7

// ---------------- device state (scratch; no allocations allowed) ----------------
__device__ float g_c[2][H];          // cell states, in-place per layer
__device__ float g_h[2][2][H];       // [buffer][layer][H], ping-pong
__device__ float g_inputs[H];
__device__ float g_anchors[NNODES + 2][H];
__device__ float g_anchors_w1[NNODES + 2][H];
__device__ float g_hw[H];
__device__ float g_lp, g_ent;
__device__ int   g_arc[4 * NNODES];

// ---------------- helpers ----------------
__device__ __forceinline__ float warp_reduce(float v) {
#pragma unroll
    for (int o = 16; o > 0; o >>= 1) v += __shfl_down_sync(0xffffffffu, v, o);
    return v;
}

__device__ __forceinline__ float sigf(float x) { return 1.0f / (1.0f + expf(-x)); }

// ---------------- threefry2x32 (exact JAX semantics) ----------------
__device__ __forceinline__ void threefry2x32(uint32_t k0, uint32_t k1,
                                             uint32_t x0, uint32_t x1,
                                             uint32_t& o0, uint32_t& o1) {
    uint32_t ks0 = k0, ks1 = k1, ks2 = k0 ^ k1 ^ 0x1BD11BDAu;
    x0 += ks0; x1 += ks1;
#define TF_ROUND(r) { x0 += x1; x1 = (x1 << (r)) | (x1 >> (32 - (r))); x1 ^= x0; }
    // i=0: rotations A = {13,15,26,6}
    TF_ROUND(13) TF_ROUND(15) TF_ROUND(26) TF_ROUND(6)
    x0 += ks1; x1 += ks2 + 1u;
    // i=1: rotations B = {17,29,16,24}
    TF_ROUND(17) TF_ROUND(29) TF_ROUND(16) TF_ROUND(24)
    x0 += ks2; x1 += ks0 + 2u;
    // i=2: rotations A
    TF_ROUND(13) TF_ROUND(15) TF_ROUND(26) TF_ROUND(6)
    x0 += ks0; x1 += ks1 + 3u;
    // i=3: rotations B
    TF_ROUND(17) TF_ROUND(29) TF_ROUND(16) TF_ROUND(24)
    x0 += ks1; x1 += ks2 + 4u;
    // i=4: rotations A
    TF_ROUND(13) TF_ROUND(15) TF_ROUND(26) TF_ROUND(6)
    x0 += ks2; x1 += ks0 + 5u;
#undef TF_ROUND
    o0 = x0; o1 = x1;
}

__device__ __forceinline__ float gumbel_from_bits(uint32_t b) {
    // jax.random.uniform(minval=tiny, maxval=1) for f32:
    // f = bitcast((b>>9)|0x3f800000) - 1;  u = f + tiny  (== max(tiny, f*(1-tiny)+tiny))
    float f = __uint_as_float((b >> 9) | 0x3f800000u) - 1.0f;
    float u = f + 1.17549435e-38f;
    return -logf(-logf(u));
}

// Exact JAX sampling: fold_in(key(42), t) then categorical (gumbel argmax),
// plus log_softmax / entropy accumulation identical to the reference.
// NOTE: uses the PARTITIONABLE threefry random_bits scheme (JAX >= 0.5.0
// default): bits[i] = o0 ^ o1 with counter pair (hi32(i)=0, lo32(i)=i).
__device__ void sample_common(float* l, int n, int t, int slot) {
    float m = -1e30f;
    for (int i = 0; i < n; i++) m = fmaxf(m, l[i]);
    float lpv[NOPS + 1];
    float se = 0.0f;
    for (int i = 0; i < n; i++) { lpv[i] = l[i] - m; se += expf(lpv[i]); }
    float lse = logf(se);
    float ent_term = 0.0f;
    for (int i = 0; i < n; i++) { lpv[i] -= lse; ent_term += lpv[i] * expf(lpv[i]); }

    // fold_in: new key = threefry([0,42], threefry_seed(t) = [0,t])
    uint32_t k0, k1;
    threefry2x32(0u, 42u, 0u, (uint32_t)t, k0, k1);

    // partitionable random_bits over flat u64 iota, 32-bit output = o0 ^ o1
    float best = -1e30f; int bi = 0;
    for (int i = 0; i < n; i++) {
        uint32_t o0, o1;
        threefry2x32(k0, k1, 0u, (uint32_t)i, o0, o1);
        float z = l[i] + gumbel_from_bits(o0 ^ o1);
        if (z > best) { best = z; bi = i; }
    }
    g_lp += lpv[bi];
    g_ent -= ent_term;
    g_arc[slot] = bi;
}

// ---------------- init ----------------
__global__ void init_kernel(const float* __restrict__ w_emb) {
    int i = blockIdx.x * blockDim.x + threadIdx.x;   // 72*256 = 18432 threads
    if (i < (NNODES + 2) * H) ((float*)g_anchors)[i] = 0.0f;
    if (i < 2 * H) ((float*)g_c)[i] = 0.0f;
    if (i < 4 * H) ((float*)g_h)[i] = 0.0f;
    if (i < H) g_inputs[i] = w_emb[NOPS * H + i];
    if (i == 0) { g_lp = 0.0f; g_ent = 0.0f; }
}

// ---------------- fused LSTM cell ----------------
// One block per output element j (0..2047). 8 warps: warps 0-3 compute the
// four gate rows of W_ih (dot with x), warps 4-7 the four rows of W_hh (dot
// with h_prev). Thread 0 fuses the full i/f/g/o cell update.
__global__ void __launch_bounds__(256) lstm_cell_kernel(
    const float* __restrict__ Wih, const float* __restrict__ Whh,
    const float* __restrict__ bih, const float* __restrict__ bhh,
    int layer, int src, int cur) {
    int j = blockIdx.x;
    int w = threadIdx.x >> 5, lane = threadIdx.x & 31;
    const float* x  = (src == 0) ? g_inputs : g_h[cur ^ 1][0];
    const float* hp = g_h[cur][layer];

    __shared__ float s[8];
    int gate = w & 3;
    const float* row = ((w < 4) ? Wih : Whh) + (size_t)(gate * H + j) * H;
    const float* vec = (w < 4) ? x : hp;
    const float4* r4 = (const float4*)row;
    const float4* v4 = (const float4*)vec;
    float acc = 0.0f;
#pragma unroll
    for (int i = 0; i < 16; i++) {
        float4 a = r4[lane + 32 * i];
        float4 b = v4[lane + 32 * i];
        acc += a.x * b.x + a.y * b.y + a.z * b.z + a.w * b.w;
    }
    acc = warp_reduce(acc);
    if (lane == 0) s[w] = acc;
    __syncthreads();
    if (threadIdx.x == 0) {
        float gi = s[0] + s[4] + bih[0 * H + j] + bhh[0 * H + j];
        float gf = s[1] + s[5] + bih[1 * H + j] + bhh[1 * H + j];
        float gg = s[2] + s[6] + bih[2 * H + j] + bhh[2 * H + j];
        float go = s[3] + s[7] + bih[3 * H + j] + bhh[3 * H + j];
        float c  = g_c[layer][j];
        float c2 = sigf(gf) * c + sigf(gi) * tanhf(gg);
        float h2 = sigf(go) * tanhf(c2);
        g_c[layer][j] = c2;
        g_h[cur ^ 1][layer][j] = h2;
    }
}

// ---------------- 2048x2048 matvec: out[r] = dot(M[r,:], h1) ----------------
// dst_sel: 0 -> g_hw, 1 -> g_anchors_w1[dst_idx]
__global__ void __launch_bounds__(256) matvec2048_kernel(
    const float* __restrict__ M, int dst_sel, int dst_idx, int cur) {
    int r = blockIdx.x * 8 + (threadIdx.x >> 5);
    int lane = threadIdx.x & 31;
    const float* v = g_h[cur][1];
    const float4* r4 = (const float4*)(M + (size_t)r * H);
    const float4* v4 = (const float4*)v;
    float acc = 0.0f;
#pragma unroll
    for (int i = 0; i < 16; i++) {
        float4 a = r4[lane + 32 * i];
        float4 b = v4[lane + 32 * i];
        acc += a.x * b.x + a.y * b.y + a.z * b.z + a.w * b.w;
    }
    acc = warp_reduce(acc);
    if (lane == 0) {
        if (dst_sel == 0) g_hw[r] = acc;
        else              g_anchors_w1[dst_idx][r] = acc;
    }
}

// ---------------- node-predecessor sampling ----------------
__global__ void __launch_bounds__(256) sample_node_kernel(
    const float* __restrict__ v_attn, int n, int t, int slot) {
    __shared__ float logits[8];
    __shared__ int s_idx;
    int w = threadIdx.x >> 5, lane = threadIdx.x & 31;
    if (w < n) {
        const float* aw = g_anchors_w1[w];
        float acc = 0.0f;
        for (int i = lane; i < H; i += 32)
            acc += v_attn[i] * tanhf(aw[i] + g_hw[i]);
        acc = warp_reduce(acc);
        if (lane == 0) logits[w] = acc;
    }
    __syncthreads();
    if (threadIdx.x == 0) {
        float l[8];
        for (int i = 0; i < n; i++) l[i] = 2.5f * tanhf(logits[i] / 5.0f);
        sample_common(l, n, t, slot);
        s_idx = g_arc[slot];
    }
    __syncthreads();
    const float* src = g_anchors[s_idx];
    for (int i = threadIdx.x; i < H; i += 256) g_inputs[i] = src[i];
}

// ---------------- op sampling ----------------
__global__ void __launch_bounds__(256) sample_op_kernel(
    const float* __restrict__ w_soft_w, const float* __restrict__ w_soft_b,
    const float* __restrict__ w_emb, int t, int slot, int cur) {
    __shared__ float logits[8];
    __shared__ int s_idx;
    int w = threadIdx.x >> 5, lane = threadIdx.x & 31;
    const float* h1 = g_h[cur][1];
    {
        const float* row = w_soft_w + (size_t)w * H;
        float acc = 0.0f;
        for (int i = lane; i < H; i += 32) acc += row[i] * h1[i];
        acc = warp_reduce(acc);
        if (lane == 0) logits[w] = acc + w_soft_b[w];
    }
    __syncthreads();
    if (threadIdx.x == 0) {
        float l[8];
        for (int i = 0; i < 8; i++) l[i] = tanhf(logits[i] / 5.0f);  // TANH_C/OP_TANH_RED = 1
        sample_common(l, 8, t, slot);
        s_idx = g_arc[slot];
    }
    __syncthreads();
    const float* src = w_emb + (size_t)s_idx * H;
    for (int i = threadIdx.x; i < H; i += 256) g_inputs[i] = src[i];
}

// ---------------- anchor registration ----------------
__global__ void anchor_fin_kernel(int k, int cur, const float* __restrict__ w_emb) {
    int i = blockIdx.x * blockDim.x + threadIdx.x;
    if (i < H) {
        g_anchors[k][i] = g_h[cur][1][i];
        g_inputs[i] = w_emb[NOPS * H + i];
    }
}

// ---------------- finalize: out = [arc(28), log_p, entropy] ----------------
__global__ void finalize_kernel(float* __restrict__ out) {
    int i = threadIdx.x;
    if (i < 28) out[i] = (float)g_arc[i];
    if (i == 28) out[28] = g_lp;
    if (i == 29) out[29] = g_ent;
}

// ---------------- host driver (graph-capturable: launches only) ----------------
extern "C" void kernel_launch(void* const* d_in, const int* in_sizes, int n_in,
                              void* d_out, int out_size) {
    const float* w_emb    = (const float*)d_in[0];
    const float* emb_attn = (const float*)d_in[1];
    const float* hid_attn = (const float*)d_in[2];
    const float* v_attn   = (const float*)d_in[3];
    const float* w_soft_w = (const float*)d_in[4];
    const float* w_soft_b = (const float*)d_in[5];
    const float* w_ih     = (const float*)d_in[6];
    const float* w_hh     = (const float*)d_in[7];
    const float* b_ih     = (const float*)d_in[8];
    const float* b_hh     = (const float*)d_in[9];
    float* out = (float*)d_out;

    init_kernel<<<72, 256>>>(w_emb);

    int cur = 0;
    auto step = [&]() {
        for (int l = 0; l < 2; l++) {
            lstm_cell_kernel<<<H, 256>>>(
                w_ih + (size_t)l * 4 * H * H,
                w_hh + (size_t)l * 4 * H * H,
                b_ih + (size_t)l * 4 * H,
                b_hh + (size_t)l * 4 * H,
                l, l, cur);
        }
        cur ^= 1;
    };

    // warm-up: two steps registering zero anchors + their attn projections
    for (int k = 0; k < 2; k++) {
        step();
        matvec2048_kernel<<<256, 256>>>(emb_attn, 1, k, cur);
    }

    int t = 0;
    for (int nid = 0; nid < NNODES; nid++) {
        // two predecessor-node decisions
        for (int j = 0; j < 2; j++) {
            step();
            matvec2048_kernel<<<256, 256>>>(hid_attn, 0, 0, cur);
            sample_node_kernel<<<1, 256>>>(v_attn, nid + 2, t, 4 * nid + 2 * j);
            t++;
        }
        // two op decisions
        for (int j = 0; j < 2; j++) {
            step();
            sample_op_kernel<<<1, 256>>>(w_soft_w, w_soft_b, w_emb, t,
                                         4 * nid + 1 + 2 * j, cur);
            t++;
        }
        // register new anchor
        step();
        matvec2048_kernel<<<256, 256>>>(emb_attn, 1, nid + 2, cur);
        anchor_fin_kernel<<<8, 256>>>(nid + 2, cur, w_emb);
    }

    finalize_kernel<<<1, 32>>>(out);
}

// round 3
// speedup vs baseline: 1.2765x; 1.2765x over previous
#include <cuda_runtime.h>
#include <cuda_fp16.h>
#include <math.h>
#include <stdint.h>

#define H 2048
#define NOPS 8
#define NNODES 7

// ---------------- device state (scratch; no allocations allowed) ----------------
__device__ float g_c[2][H];
__device__ float g_h[2][2][H];       // [buffer][layer][H], ping-pong
__device__ float g_inputs[H];
__device__ float g_anchors[NNODES + 2][H];
__device__ float g_anchors_w1[NNODES + 2][H];
__device__ float g_hw[H];
__device__ float g_lp, g_ent;
__device__ int   g_arc[4 * NNODES];

// fp16 staged weights (converted from inputs once per replay)
__device__ __half g_wih_h[2 * 4 * H * H];   // 67 MB
__device__ __half g_whh_h[2 * 4 * H * H];   // 67 MB
__device__ __half g_emba_h[H * H];          // 8.4 MB
__device__ __half g_hida_h[H * H];          // 8.4 MB

// ---------------- helpers ----------------
__device__ __forceinline__ float warp_reduce(float v) {
#pragma unroll
    for (int o = 16; o > 0; o >>= 1) v += __shfl_down_sync(0xffffffffu, v, o);
    return v;
}

__device__ __forceinline__ float sigf(float x) { return 1.0f / (1.0f + expf(-x)); }

// ---------------- threefry2x32 (exact JAX semantics) ----------------
__device__ __forceinline__ void threefry2x32(uint32_t k0, uint32_t k1,
                                             uint32_t x0, uint32_t x1,
                                             uint32_t& o0, uint32_t& o1) {
    uint32_t ks0 = k0, ks1 = k1, ks2 = k0 ^ k1 ^ 0x1BD11BDAu;
    x0 += ks0; x1 += ks1;
#define TF_ROUND(r) { x0 += x1; x1 = (x1 << (r)) | (x1 >> (32 - (r))); x1 ^= x0; }
    TF_ROUND(13) TF_ROUND(15) TF_ROUND(26) TF_ROUND(6)
    x0 += ks1; x1 += ks2 + 1u;
    TF_ROUND(17) TF_ROUND(29) TF_ROUND(16) TF_ROUND(24)
    x0 += ks2; x1 += ks0 + 2u;
    TF_ROUND(13) TF_ROUND(15) TF_ROUND(26) TF_ROUND(6)
    x0 += ks0; x1 += ks1 + 3u;
    TF_ROUND(17) TF_ROUND(29) TF_ROUND(16) TF_ROUND(24)
    x0 += ks1; x1 += ks2 + 4u;
    TF_ROUND(13) TF_ROUND(15) TF_ROUND(26) TF_ROUND(6)
    x0 += ks2; x1 += ks0 + 5u;
#undef TF_ROUND
    o0 = x0; o1 = x1;
}

__device__ __forceinline__ float gumbel_from_bits(uint32_t b) {
    float f = __uint_as_float((b >> 9) | 0x3f800000u) - 1.0f;
    float u = f + 1.17549435e-38f;
    return -logf(-logf(u));
}

// Exact JAX sampling (partitionable threefry): bits[i] = o0 ^ o1,
// counter = (0, i); key = fold_in(key(42), t) = threefry([0,42],[0,t]).
__device__ void sample_common(float* l, int n, int t, int slot) {
    float m = -1e30f;
    for (int i = 0; i < n; i++) m = fmaxf(m, l[i]);
    float lpv[NOPS + 1];
    float se = 0.0f;
    for (int i = 0; i < n; i++) { lpv[i] = l[i] - m; se += expf(lpv[i]); }
    float lse = logf(se);
    float ent_term = 0.0f;
    for (int i = 0; i < n; i++) { lpv[i] -= lse; ent_term += lpv[i] * expf(lpv[i]); }

    uint32_t k0, k1;
    threefry2x32(0u, 42u, 0u, (uint32_t)t, k0, k1);

    float best = -1e30f; int bi = 0;
    for (int i = 0; i < n; i++) {
        uint32_t o0, o1;
        threefry2x32(k0, k1, 0u, (uint32_t)i, o0, o1);
        float z = l[i] + gumbel_from_bits(o0 ^ o1);
        if (z > best) { best = z; bi = i; }
    }
    g_lp += lpv[bi];
    g_ent -= ent_term;
    g_arc[slot] = bi;
}

// ---------------- fp32 -> fp16 conversion (runs once per replay) ----------------
__global__ void __launch_bounds__(256) convert_fp16_kernel(
    const float* __restrict__ src, __half* __restrict__ dst, int n8) {
    int i = blockIdx.x * blockDim.x + threadIdx.x;
    int stride = gridDim.x * blockDim.x;
    const float4* s4 = (const float4*)src;
    uint4* d4 = (uint4*)dst;
    for (; i < n8; i += stride) {
        float4 a = s4[2 * i];
        float4 b = s4[2 * i + 1];
        __half2 h0 = __floats2half2_rn(a.x, a.y);
        __half2 h1 = __floats2half2_rn(a.z, a.w);
        __half2 h2 = __floats2half2_rn(b.x, b.y);
        __half2 h3 = __floats2half2_rn(b.z, b.w);
        uint4 q;
        q.x = *reinterpret_cast<uint32_t*>(&h0);
        q.y = *reinterpret_cast<uint32_t*>(&h1);
        q.z = *reinterpret_cast<uint32_t*>(&h2);
        q.w = *reinterpret_cast<uint32_t*>(&h3);
        d4[i] = q;
    }
}

// ---------------- init ----------------
__global__ void init_kernel(const float* __restrict__ w_emb) {
    int i = blockIdx.x * blockDim.x + threadIdx.x;
    if (i < (NNODES + 2) * H) ((float*)g_anchors)[i] = 0.0f;
    if (i < 2 * H) ((float*)g_c)[i] = 0.0f;
    if (i < 4 * H) ((float*)g_h)[i] = 0.0f;
    if (i < H) g_inputs[i] = w_emb[NOPS * H + i];
    if (i == 0) { g_lp = 0.0f; g_ent = 0.0f; }
}

// ---------------- fused LSTM cell (fp16 weights, fp32 accumulate) ----------------
// One block per output element j. 4 warps, warp w = gate w (i,f,g,o).
// Each warp computes dot(Wih_row, x) + dot(Whh_row, h) with the activation
// vectors staged in shared memory, so global loads are pure matrix-row
// streams (unroll-8 uint4 = full 4KB row in flight -> high MLP).
__global__ void __launch_bounds__(128) lstm_cell_kernel(
    const __half* __restrict__ Wih, const __half* __restrict__ Whh,
    const float* __restrict__ bih, const float* __restrict__ bhh,
    int layer, int src, int cur) {
    int j = blockIdx.x;
    int tid = threadIdx.x, w = tid >> 5, lane = tid & 31;
    __shared__ float xs[H], hs[H];
    __shared__ float sred[4];

    const float* x  = (src == 0) ? g_inputs : g_h[cur ^ 1][0];
    const float* hp = g_h[cur][layer];
    float4* xs4 = (float4*)xs; float4* hs4 = (float4*)hs;
    const float4* x4 = (const float4*)x; const float4* h4 = (const float4*)hp;
#pragma unroll
    for (int i = tid; i < H / 4; i += 128) { xs4[i] = x4[i]; hs4[i] = h4[i]; }

    float bsum = bih[w * H + j] + bhh[w * H + j];
    float cprev = (tid == 0) ? g_c[layer][j] : 0.0f;
    __syncthreads();

    const uint4* rA = (const uint4*)(Wih + ((size_t)w * H + j) * H);
    const uint4* rB = (const uint4*)(Whh + ((size_t)w * H + j) * H);
    float acc = 0.0f;
#pragma unroll
    for (int i = 0; i < 8; i++) {
        uint4 q = rA[i * 32 + lane];
        int base = (i * 32 + lane) * 8;
        const __half2* hh = (const __half2*)&q;
#pragma unroll
        for (int p = 0; p < 4; p++) {
            float2 f = __half22float2(hh[p]);
            acc += f.x * xs[base + 2 * p] + f.y * xs[base + 2 * p + 1];
        }
    }
#pragma unroll
    for (int i = 0; i < 8; i++) {
        uint4 q = rB[i * 32 + lane];
        int base = (i * 32 + lane) * 8;
        const __half2* hh = (const __half2*)&q;
#pragma unroll
        for (int p = 0; p < 4; p++) {
            float2 f = __half22float2(hh[p]);
            acc += f.x * hs[base + 2 * p] + f.y * hs[base + 2 * p + 1];
        }
    }
    acc = warp_reduce(acc);
    if (lane == 0) sred[w] = acc + bsum;
    __syncthreads();
    if (tid == 0) {
        float c2 = sigf(sred[1]) * cprev + sigf(sred[0]) * tanhf(sred[2]);
        float h2 = sigf(sred[3]) * tanhf(c2);
        g_c[layer][j] = c2;
        g_h[cur ^ 1][layer][j] = h2;
    }
}

// ---------------- 2048x2048 fp16 matvec: out[r] = dot(M[r,:], h1) ----------------
// dst_sel: 0 -> g_hw, 1 -> g_anchors_w1[dst_idx].
// fin_k >= 0: also register anchor fin_k (copy h1 -> anchors, reset inputs).
__global__ void __launch_bounds__(256) matvec_kernel(
    const __half* __restrict__ M, int dst_sel, int dst_idx, int cur,
    int fin_k, const float* __restrict__ w_emb) {
    __shared__ float vs[H];
    int tid = threadIdx.x, w = tid >> 5, lane = tid & 31;
    const float* v = g_h[cur][1];
#pragma unroll
    for (int i = tid; i < H / 4; i += 256) ((float4*)vs)[i] = ((const float4*)v)[i];
    __syncthreads();

    int r = blockIdx.x * 8 + w;
    const uint4* row = (const uint4*)(M + (size_t)r * H);
    float acc = 0.0f;
#pragma unroll
    for (int i = 0; i < 8; i++) {
        uint4 q = row[i * 32 + lane];
        int base = (i * 32 + lane) * 8;
        const __half2* hh = (const __half2*)&q;
#pragma unroll
        for (int p = 0; p < 4; p++) {
            float2 f = __half22float2(hh[p]);
            acc += f.x * vs[base + 2 * p] + f.y * vs[base + 2 * p + 1];
        }
    }
    acc = warp_reduce(acc);
    if (lane == 0) {
        if (dst_sel == 0) g_hw[r] = acc;
        else              g_anchors_w1[dst_idx][r] = acc;
    }
    if (fin_k >= 0 && tid < 8) {
        int rr = blockIdx.x * 8 + tid;
        g_anchors[fin_k][rr] = vs[rr];
        g_inputs[rr] = w_emb[NOPS * H + rr];
    }
}

// ---------------- node-predecessor sampling ----------------
__global__ void __launch_bounds__(256) sample_node_kernel(
    const float* __restrict__ v_attn, int n, int t, int slot) {
    __shared__ float logits[8];
    __shared__ int s_idx;
    int w = threadIdx.x >> 5, lane = threadIdx.x & 31;
    if (w < n) {
        const float4* aw = (const float4*)g_anchors_w1[w];
        const float4* hw = (const float4*)g_hw;
        const float4* va = (const float4*)v_attn;
        float acc = 0.0f;
#pragma unroll
        for (int i = lane; i < H / 4; i += 32) {
            float4 a = aw[i], b = hw[i], c = va[i];
            acc += c.x * tanhf(a.x + b.x) + c.y * tanhf(a.y + b.y)
                 + c.z * tanhf(a.z + b.z) + c.w * tanhf(a.w + b.w);
        }
        acc = warp_reduce(acc);
        if (lane == 0) logits[w] = acc;
    }
    __syncthreads();
    if (threadIdx.x == 0) {
        float l[8];
        for (int i = 0; i < n; i++) l[i] = 2.5f * tanhf(logits[i] / 5.0f);
        sample_common(l, n, t, slot);
        s_idx = g_arc[slot];
    }
    __syncthreads();
    const float* src = g_anchors[s_idx];
    for (int i = threadIdx.x; i < H; i += 256) g_inputs[i] = src[i];
}

// ---------------- op sampling ----------------
__global__ void __launch_bounds__(256) sample_op_kernel(
    const float* __restrict__ w_soft_w, const float* __restrict__ w_soft_b,
    const float* __restrict__ w_emb, int t, int slot, int cur) {
    __shared__ float logits[8];
    __shared__ int s_idx;
    int w = threadIdx.x >> 5, lane = threadIdx.x & 31;
    {
        const float4* row = (const float4*)(w_soft_w + (size_t)w * H);
        const float4* h1 = (const float4*)g_h[cur][1];
        float acc = 0.0f;
#pragma unroll
        for (int i = lane; i < H / 4; i += 32) {
            float4 a = row[i], b = h1[i];
            acc += a.x * b.x + a.y * b.y + a.z * b.z + a.w * b.w;
        }
        acc = warp_reduce(acc);
        if (lane == 0) logits[w] = acc + w_soft_b[w];
    }
    __syncthreads();
    if (threadIdx.x == 0) {
        float l[8];
        for (int i = 0; i < 8; i++) l[i] = tanhf(logits[i] / 5.0f);  // TANH_C/OP_TANH_RED = 1
        sample_common(l, 8, t, slot);
        s_idx = g_arc[slot];
    }
    __syncthreads();
    const float* src = w_emb + (size_t)s_idx * H;
    for (int i = threadIdx.x; i < H; i += 256) g_inputs[i] = src[i];
}

// ---------------- finalize: out = [arc(28), log_p, entropy] ----------------
__global__ void finalize_kernel(float* __restrict__ out) {
    int i = threadIdx.x;
    if (i < 28) out[i] = (float)g_arc[i];
    if (i == 28) out[28] = g_lp;
    if (i == 29) out[29] = g_ent;
}

// ---------------- host driver (graph-capturable: launches only) ----------------
extern "C" void kernel_launch(void* const* d_in, const int* in_sizes, int n_in,
                              void* d_out, int out_size) {
    const float* w_emb    = (const float*)d_in[0];
    const float* emb_attn = (const float*)d_in[1];
    const float* hid_attn = (const float*)d_in[2];
    const float* v_attn   = (const float*)d_in[3];
    const float* w_soft_w = (const float*)d_in[4];
    const float* w_soft_b = (const float*)d_in[5];
    const float* w_ih     = (const float*)d_in[6];
    const float* w_hh     = (const float*)d_in[7];
    const float* b_ih     = (const float*)d_in[8];
    const float* b_hh     = (const float*)d_in[9];
    float* out = (float*)d_out;

    // fp16 staging of all large weight matrices (device-symbol destinations)
    __half* wih_h; cudaGetSymbolAddress((void**)&wih_h, g_wih_h);
    __half* whh_h; cudaGetSymbolAddress((void**)&whh_h, g_whh_h);
    __half* emba_h; cudaGetSymbolAddress((void**)&emba_h, g_emba_h);
    __half* hida_h; cudaGetSymbolAddress((void**)&hida_h, g_hida_h);

    convert_fp16_kernel<<<4096, 256>>>(w_ih, wih_h, 2 * 4 * H * H / 8);
    convert_fp16_kernel<<<4096, 256>>>(w_hh, whh_h, 2 * 4 * H * H / 8);
    convert_fp16_kernel<<<1024, 256>>>(emb_attn, emba_h, H * H / 8);
    convert_fp16_kernel<<<1024, 256>>>(hid_attn, hida_h, H * H / 8);

    init_kernel<<<72, 256>>>(w_emb);

    int cur = 0;
    auto step = [&]() {
        for (int l = 0; l < 2; l++) {
            lstm_cell_kernel<<<H, 128>>>(
                wih_h + (size_t)l * 4 * H * H,
                whh_h + (size_t)l * 4 * H * H,
                b_ih + (size_t)l * 4 * H,
                b_hh + (size_t)l * 4 * H,
                l, l, cur);
        }
        cur ^= 1;
    };

    // warm-up: two steps registering zero anchors + their attn projections
    for (int k = 0; k < 2; k++) {
        step();
        matvec_kernel<<<256, 256>>>(emba_h, 1, k, cur, -1, w_emb);
    }

    int t = 0;
    for (int nid = 0; nid < NNODES; nid++) {
        for (int j = 0; j < 2; j++) {
            step();
            matvec_kernel<<<256, 256>>>(hida_h, 0, 0, cur, -1, w_emb);
            sample_node_kernel<<<1, 256>>>(v_attn, nid + 2, t, 4 * nid + 2 * j);
            t++;
        }
        for (int j = 0; j < 2; j++) {
            step();
            sample_op_kernel<<<1, 256>>>(w_soft_w, w_soft_b, w_emb, t,
                                         4 * nid + 1 + 2 * j, cur);
            t++;
        }
        // final step: register new anchor (copy fused into matvec epilogue)
        step();
        matvec_kernel<<<256, 256>>>(emba_h, 1, nid + 2, cur, nid + 2, w_emb);
    }

    finalize_kernel<<<1, 32>>>(out);
}